// round 10
// baseline (speedup 1.0000x reference)
#include <cuda_runtime.h>
#include <cstdint>

// Problem constants (fixed by the reference)
#define NB  32
#define MP  30
#define KJ  17
#define KHW (17 * 256 * 256)   // 1114112
#define MK  (MP * KJ)          // 510  joints per image
#define NI4 (MK * 2 / 4)       // 255  int4 words of joints per image
#define MU_INVALID 1e18f       // sentinel: exp(-(d^2)) underflows to 0

// One warp per batch image — best-measured configuration (R4 = 6.62us):
//  * coalesced int4 joints load (8 iters/lane)
//  * visibility-predicated tag gather (halves DRAM gather lines)
//  * float2 (v, t) smem pairs (one STS.64 per joint)
//  * sentinel-mu rotation push: 15 shfls, symmetry-halved, no diagonal
//  * ballot-based valid-person count
//  * pull butterfly hoisted to overlap the MUFU push loop
//  * dual-lane output store (butterfly leaves sums in all lanes)
// NOTE: redux.sync.add.f32 is NOT available on sm_103a (R9 post-mortem).
__global__ __launch_bounds__(32, 1)
void ae_loss_kernel(const float* __restrict__ tags,
                    const int*   __restrict__ joints,
                    float*       __restrict__ out) {
    const int n = blockIdx.x;
    const float* tg = tags + (size_t)n * KHW;
    const int4*  j4 = reinterpret_cast<const int4*>(joints + (size_t)n * MK * 2);

    const int lane = threadIdx.x;

    __shared__ float2 s_pair[MK];   // (v, v*t) per joint

    // ---- Phase A: coalesced joints load + predicated gather ----
    #pragma unroll
    for (int w = 0; w < 8; w++) {
        int m = lane + 32 * w;                  // int4 index = joints 2m, 2m+1
        if (m < NI4) {
            int4 q = __ldg(&j4[m]);
            float v0 = (q.y > 0) ? 1.0f : 0.0f;
            float v1 = (q.w > 0) ? 1.0f : 0.0f;
            float t0 = 0.0f, t1 = 0.0f;
            if (q.y > 0) t0 = __ldg(tg + q.x);  // skip invisible joints
            if (q.w > 0) t1 = __ldg(tg + q.z);
            s_pair[2 * m]     = make_float2(v0, t0);
            s_pair[2 * m + 1] = make_float2(v1, t1);
        }
    }
    __syncwarp();

    // ---- Phase B: per-person stats (lane p owns person p) ----
    float mu = MU_INVALID, pvf = 0.0f, pull = 0.0f;
    if (lane < MP) {
        float cnt = 0.0f, s1 = 0.0f, s2 = 0.0f;
        #pragma unroll
        for (int k = 0; k < KJ; k++) {
            float2 pr = s_pair[lane * KJ + k];
            cnt += pr.x;
            s1  += pr.y;
            s2  += pr.y * pr.y;                 // t pre-masked; v in {0,1}
        }
        if (cnt > 0.0f) {
            float rcs = __fdividef(1.0f, cnt);
            mu   = s1 * rcs;
            pvf  = 1.0f;
            pull = fmaxf(s2 - cnt * mu * mu, 0.0f) * rcs;
        }
    }

    // n (valid-person count) via ballot.
    unsigned bal = __ballot_sync(0xffffffffu, pvf > 0.0f);
    float nn = (float)__popc(bal);

    // Pull butterfly hoisted: its dependent SHFL chain overlaps the push loop.
    #pragma unroll
    for (int o = 16; o > 0; o >>= 1)
        pull += __shfl_xor_sync(0xffffffffu, pull, o);

    // ---- Phase C: push via rotation, symmetry-halved, sentinel-masked ----
    // ordered off-diagonal sum = 2*sum(off=1..14) + sum(off=15);
    // invalid persons carry mu=1e18 -> exp underflows to exactly 0.
    float psum2 = 0.0f, psum1 = 0.0f;
    #pragma unroll
    for (int off = 1; off <= 15; off++) {
        int src = lane + off;
        if (src >= MP) src -= MP;
        float muj = __shfl_sync(0xffffffffu, mu, src);
        float d = mu - muj;
        float term = __expf(-d * d);
        if (off < 15) psum2 += term; else psum1 = term;
    }
    float psum = pvf * fmaf(2.0f, psum2, psum1);

    // ---- Push butterfly ----
    #pragma unroll
    for (int o = 16; o > 0; o >>= 1)
        psum += __shfl_xor_sync(0xffffffffu, psum, o);

    // Butterfly leaves full sums in ALL lanes: two lanes store in parallel.
    if (lane == 0) {
        float denom = fmaxf((nn - 1.0f) * nn, 1.0f);
        out[n] = psum * __fdividef(0.5f, denom);                 // pushes [0..31]
    } else if (lane == 1) {
        out[NB + n] = pull * __fdividef(1.0f, fmaxf(nn, 1.0f));  // pulls [32..63]
    }
}

extern "C" void kernel_launch(void* const* d_in, const int* in_sizes, int n_in,
                              void* d_out, int out_size) {
    const float* tags   = (const float*)d_in[0];  // [N, KHW, 1] float32
    const int*   joints = (const int*)d_in[1];    // [N, M, K, 2] int32
    float* out = (float*)d_out;                   // [2*N] = pushes ++ pulls
    ae_loss_kernel<<<NB, 32>>>(tags, joints, out);
}

// round 11
// speedup vs baseline: 1.0385x; 1.0385x over previous
#include <cuda_runtime.h>
#include <cstdint>

// Problem constants (fixed by the reference)
#define NB  32
#define MP  30
#define KJ  17
#define KHW (17 * 256 * 256)   // 1114112
#define MK  (MP * KJ)          // 510  joints per image
#define NI4 (MK * 2 / 4)       // 255  int4 words of joints per image

// FINAL kernel — best-measured configuration (R4: 6.62us).
// One warp per batch image:
//  * coalesced int4 joints load (8 iterations/lane)
//  * visibility-predicated tag gather (halves gather DRAM lines)
//  * float2 (v, t) smem pairs (one STS.64 per joint)
//  * rotation push loop, symmetry-halved (15 iterations, no diagonal term)
//  * 3-value warp butterfly reduce, single-lane store
// Measured floor: dur_us ~6.6-6.9 is dominated by graph-replay/launch
// overhead + two serial data-dependent memory round trips; all pipes <1%.
// (redux.sync.add.f32 is NOT supported by sm_103a ptxas — R9.)
__global__ __launch_bounds__(32, 1)
void ae_loss_kernel(const float* __restrict__ tags,
                    const int*   __restrict__ joints,
                    float*       __restrict__ out) {
    const int n = blockIdx.x;
    const float* tg = tags + (size_t)n * KHW;
    const int4*  j4 = reinterpret_cast<const int4*>(joints + (size_t)n * MK * 2);

    const int lane = threadIdx.x;

    __shared__ float2 s_pair[MK];   // (v, v*t) per joint

    // ---- Phase A: coalesced joints load, predicated gather, scatter to smem ----
    #pragma unroll
    for (int w = 0; w < 8; w++) {
        int m = lane + 32 * w;                  // int4 index = joints 2m, 2m+1
        if (m < NI4) {
            int4 q = __ldg(&j4[m]);
            float v0 = (q.y > 0) ? 1.0f : 0.0f;
            float v1 = (q.w > 0) ? 1.0f : 0.0f;
            float t0 = 0.0f, t1 = 0.0f;
            if (q.y > 0) t0 = __ldg(tg + q.x);  // skip invisible joints
            if (q.w > 0) t1 = __ldg(tg + q.z);
            s_pair[2 * m]     = make_float2(v0, t0);
            s_pair[2 * m + 1] = make_float2(v1, t1);
        }
    }
    __syncwarp();

    // ---- Phase B: per-person stats (lane p owns person p) ----
    float mu = 0.0f, pvf = 0.0f, pull = 0.0f;
    if (lane < MP) {
        float cnt = 0.0f, s1 = 0.0f, s2 = 0.0f;
        #pragma unroll
        for (int k = 0; k < KJ; k++) {
            float2 pr = s_pair[lane * KJ + k];
            cnt += pr.x;
            s1  += pr.y;
            s2  += pr.y * pr.y;   // (v*t)^2 == v*t^2 since v in {0,1}
        }
        float cs  = fmaxf(cnt, 1.0f);
        float rcs = __fdividef(1.0f, cs);
        mu  = s1 * rcs;
        pvf = (cnt > 0.0f) ? 1.0f : 0.0f;
        pull = pvf * fmaxf(s2 - cnt * mu * mu, 0.0f) * rcs;
    }

    // ---- Phase C: push via rotation (off-diagonal only, symmetry-halved) ----
    // ordered pairs = offsets 1..29; term(off) == term(30-off) pairwise, so
    // sum = 2 * sum(off=1..14) + sum(off=15).  Diagonal never appears.
    float psum2 = 0.0f, psum1 = 0.0f;
    #pragma unroll
    for (int off = 1; off <= 15; off++) {
        int src = lane + off;
        if (src >= MP) src -= MP;
        float muj = __shfl_sync(0xffffffffu, mu,  src);
        float pvj = __shfl_sync(0xffffffffu, pvf, src);
        float d = mu - muj;
        float term = pvj * __expf(-d * d);
        if (off < 15) psum2 += term; else psum1 = term;
    }
    float psum = pvf * fmaf(2.0f, psum2, psum1);  // mask invalid persons/lanes

    // ---- Phase D: warp butterfly reduce (pull, n, push) ----
    float nn = pvf;
    #pragma unroll
    for (int o = 16; o > 0; o >>= 1) {
        pull += __shfl_xor_sync(0xffffffffu, pull, o);
        nn   += __shfl_xor_sync(0xffffffffu, nn,   o);
        psum += __shfl_xor_sync(0xffffffffu, psum, o);
    }

    if (lane == 0) {
        float denom = fmaxf((nn - 1.0f) * nn, 1.0f);
        out[n]      = psum * __fdividef(0.5f, denom);           // pushes [0..31]
        out[NB + n] = pull * __fdividef(1.0f, fmaxf(nn, 1.0f)); // pulls  [32..63]
    }
}

extern "C" void kernel_launch(void* const* d_in, const int* in_sizes, int n_in,
                              void* d_out, int out_size) {
    const float* tags   = (const float*)d_in[0];  // [N, KHW, 1] float32
    const int*   joints = (const int*)d_in[1];    // [N, M, K, 2] int32
    float* out = (float*)d_out;                   // [2*N] = pushes ++ pulls
    ae_loss_kernel<<<NB, 32>>>(tags, joints, out);
}

// round 12
// speedup vs baseline: 1.0485x; 1.0097x over previous
#include <cuda_runtime.h>
#include <cstdint>

// Problem constants (fixed by the reference)
#define NB  32
#define MP  30
#define KJ  17
#define KHW (17 * 256 * 256)   // 1114112
#define MK  (MP * KJ)          // 510  joints per image
#define NI4 (MK * 2 / 4)       // 255  int4 words of joints per image

// FINAL kernel — best-measured configuration (6.62us).
// One warp per batch image:
//  * coalesced int4 joints load (8 iterations/lane)
//  * visibility-predicated tag gather (halves gather DRAM lines: 407->205 GB/s)
//  * float2 (v, t) smem pairs (one STS.64 per joint)
//  * rotation push loop, symmetry-halved (15 iterations, no diagonal term)
//  * 3-value warp butterfly reduce, single-lane store
// Measured floor: dur_us 6.62-6.91 is graph-replay/launch overhead plus two
// serial data-dependent memory round trips; all pipes <1% utilized.
// (redux.sync.add.f32 is NOT supported by sm_103a ptxas.)
__global__ __launch_bounds__(32, 1)
void ae_loss_kernel(const float* __restrict__ tags,
                    const int*   __restrict__ joints,
                    float*       __restrict__ out) {
    const int n = blockIdx.x;
    const float* tg = tags + (size_t)n * KHW;
    const int4*  j4 = reinterpret_cast<const int4*>(joints + (size_t)n * MK * 2);

    const int lane = threadIdx.x;

    __shared__ float2 s_pair[MK];   // (v, v*t) per joint

    // ---- Phase A: coalesced joints load, predicated gather, scatter to smem ----
    #pragma unroll
    for (int w = 0; w < 8; w++) {
        int m = lane + 32 * w;                  // int4 index = joints 2m, 2m+1
        if (m < NI4) {
            int4 q = __ldg(&j4[m]);
            float v0 = (q.y > 0) ? 1.0f : 0.0f;
            float v1 = (q.w > 0) ? 1.0f : 0.0f;
            float t0 = 0.0f, t1 = 0.0f;
            if (q.y > 0) t0 = __ldg(tg + q.x);  // skip invisible joints
            if (q.w > 0) t1 = __ldg(tg + q.z);
            s_pair[2 * m]     = make_float2(v0, t0);
            s_pair[2 * m + 1] = make_float2(v1, t1);
        }
    }
    __syncwarp();

    // ---- Phase B: per-person stats (lane p owns person p) ----
    float mu = 0.0f, pvf = 0.0f, pull = 0.0f;
    if (lane < MP) {
        float cnt = 0.0f, s1 = 0.0f, s2 = 0.0f;
        #pragma unroll
        for (int k = 0; k < KJ; k++) {
            float2 pr = s_pair[lane * KJ + k];
            cnt += pr.x;
            s1  += pr.y;
            s2  += pr.y * pr.y;   // (v*t)^2 == v*t^2 since v in {0,1}
        }
        float cs  = fmaxf(cnt, 1.0f);
        float rcs = __fdividef(1.0f, cs);
        mu  = s1 * rcs;
        pvf = (cnt > 0.0f) ? 1.0f : 0.0f;
        pull = pvf * fmaxf(s2 - cnt * mu * mu, 0.0f) * rcs;
    }

    // ---- Phase C: push via rotation (off-diagonal only, symmetry-halved) ----
    // ordered pairs = offsets 1..29; term(off) == term(30-off) pairwise, so
    // sum = 2 * sum(off=1..14) + sum(off=15).  Diagonal never appears.
    float psum2 = 0.0f, psum1 = 0.0f;
    #pragma unroll
    for (int off = 1; off <= 15; off++) {
        int src = lane + off;
        if (src >= MP) src -= MP;
        float muj = __shfl_sync(0xffffffffu, mu,  src);
        float pvj = __shfl_sync(0xffffffffu, pvf, src);
        float d = mu - muj;
        float term = pvj * __expf(-d * d);
        if (off < 15) psum2 += term; else psum1 = term;
    }
    float psum = pvf * fmaf(2.0f, psum2, psum1);  // mask invalid persons/lanes

    // ---- Phase D: warp butterfly reduce (pull, n, push) ----
    float nn = pvf;
    #pragma unroll
    for (int o = 16; o > 0; o >>= 1) {
        pull += __shfl_xor_sync(0xffffffffu, pull, o);
        nn   += __shfl_xor_sync(0xffffffffu, nn,   o);
        psum += __shfl_xor_sync(0xffffffffu, psum, o);
    }

    if (lane == 0) {
        float denom = fmaxf((nn - 1.0f) * nn, 1.0f);
        out[n]      = psum * __fdividef(0.5f, denom);           // pushes [0..31]
        out[NB + n] = pull * __fdividef(1.0f, fmaxf(nn, 1.0f)); // pulls  [32..63]
    }
}

extern "C" void kernel_launch(void* const* d_in, const int* in_sizes, int n_in,
                              void* d_out, int out_size) {
    const float* tags   = (const float*)d_in[0];  // [N, KHW, 1] float32
    const int*   joints = (const int*)d_in[1];    // [N, M, K, 2] int32
    float* out = (float*)d_out;                   // [2*N] = pushes ++ pulls
    ae_loss_kernel<<<NB, 32>>>(tags, joints, out);
}